// round 1
// baseline (speedup 1.0000x reference)
#include <cuda_runtime.h>
#include <cstdint>

// ---------------------------------------------------------------------------
// Problem constants (fixed shapes from setup_inputs)
// ---------------------------------------------------------------------------
#define BATCH 1024
#define NIN   2048
#define NOUT  2048
#define NC    10
#define TSTEPS 10
#define THRESH 0.5f
#define DECAY  0.2f
// THRESH*DECAY
#define TD 0.1f

// Scratch (no cudaMalloc allowed)
__device__ float g_h[BATCH * NOUT];        // h = x @ W_enc^T   (8 MB)
__device__ float g_losspart[BATCH];        // per-batch-row loss partials

// ---------------------------------------------------------------------------
// Kernel 1: fp32 GEMM  H[b][n] = sum_k x[b][k] * W_enc[n][k]
// A: [M,K] row-major, B: [N,K] row-major (both K-contiguous => A*B^T)
// 128x128 tile, BK=16, 256 threads, 8x8 per thread.
// ---------------------------------------------------------------------------
#define BM 128
#define BN 128
#define BK 16

__global__ __launch_bounds__(256, 2)
void sgemm_nt_kernel(const float* __restrict__ A,
                     const float* __restrict__ Bw)
{
    const int K = NIN;
    const int N = NOUT;

    __shared__ float As[BK][BM + 1];
    __shared__ float Bs[BK][BN + 1];

    const int tid = threadIdx.x;
    const int m0  = blockIdx.y * BM;
    const int n0  = blockIdx.x * BN;

    // loader mapping: each thread loads 2 float4 from A and 2 from B per k-tile
    const int lr = tid >> 2;          // 0..63
    const int lc = (tid & 3) << 2;    // 0,4,8,12

    // compute mapping
    const int tx = tid & 15;          // 0..15 -> 8 cols each
    const int ty = tid >> 4;          // 0..15 -> 8 rows each

    float acc[8][8];
#pragma unroll
    for (int i = 0; i < 8; i++)
#pragma unroll
        for (int j = 0; j < 8; j++) acc[i][j] = 0.0f;

    for (int k0 = 0; k0 < K; k0 += BK) {
#pragma unroll
        for (int s = 0; s < 2; s++) {
            const int r = lr + s * 64;
            float4 va = *(const float4*)(A  + (size_t)(m0 + r) * K + k0 + lc);
            As[lc + 0][r] = va.x; As[lc + 1][r] = va.y;
            As[lc + 2][r] = va.z; As[lc + 3][r] = va.w;
            float4 vb = *(const float4*)(Bw + (size_t)(n0 + r) * K + k0 + lc);
            Bs[lc + 0][r] = vb.x; Bs[lc + 1][r] = vb.y;
            Bs[lc + 2][r] = vb.z; Bs[lc + 3][r] = vb.w;
        }
        __syncthreads();

#pragma unroll
        for (int kk = 0; kk < BK; kk++) {
            float a[8], b[8];
#pragma unroll
            for (int i = 0; i < 8; i++) a[i] = As[kk][ty * 8 + i];
#pragma unroll
            for (int j = 0; j < 8; j++) b[j] = Bs[kk][tx * 8 + j];
#pragma unroll
            for (int i = 0; i < 8; i++)
#pragma unroll
                for (int j = 0; j < 8; j++)
                    acc[i][j] = fmaf(a[i], b[j], acc[i][j]);
        }
        __syncthreads();
    }

    // store to g_h
#pragma unroll
    for (int i = 0; i < 8; i++) {
        float* crow = g_h + (size_t)(m0 + ty * 8 + i) * N + n0 + tx * 8;
#pragma unroll
        for (int j4 = 0; j4 < 2; j4++) {
            float4 v = make_float4(acc[i][j4 * 4 + 0], acc[i][j4 * 4 + 1],
                                   acc[i][j4 * 4 + 2], acc[i][j4 * 4 + 3]);
            *(float4*)(crow + j4 * 4) = v;
        }
    }
}

// ---------------------------------------------------------------------------
// Kernel 2: fused LIF recurrence + spike output + decoder GEMV + loss partial
// One block per batch row b. 256 threads, each owns 8 contiguous n.
// ---------------------------------------------------------------------------
__global__ __launch_bounds__(256, 4)
void lif_fused_kernel(const float* __restrict__ Wdec,
                      const float* __restrict__ y1h,
                      float* __restrict__ out)
{
    const int b   = blockIdx.x;
    const int tid = threadIdx.x;
    const int lane = tid & 31;
    const int wid  = tid >> 5;          // 8 warps
    const int n0  = tid * 8;

    // load h (8 contiguous floats)
    const float* hrow = g_h + (size_t)b * NOUT;
    float4 h0 = *(const float4*)(hrow + n0);
    float4 h1 = *(const float4*)(hrow + n0 + 4);
    float h[8] = {h0.x, h0.y, h0.z, h0.w, h1.x, h1.y, h1.z, h1.w};

    float mem[8], sp[8];
#pragma unroll
    for (int j = 0; j < 8; j++) { mem[j] = 0.0f; sp[j] = 0.0f; }

    __shared__ float red[8][NC];        // per-warp partial dots
    __shared__ float lsh[NC];

    // per-class recurrent state held by threads tid < NC
    float ym = 0.0f, ys = 0.0f, lossacc = 0.0f, yoh = 0.0f;
    if (tid < NC) yoh = y1h[(size_t)b * NC + tid];

    for (int t = 0; t < TSTEPS; t++) {
        // LIF membrane + spike
#pragma unroll
        for (int j = 0; j < 8; j++) {
            mem[j] = mem[j] * DECAY + h[j] - sp[j] * TD;
            sp[j]  = (mem[j] > THRESH) ? 1.0f : 0.0f;
        }
        // coalesced spike store (each thread writes 8 contiguous floats)
        float* orow = out + ((size_t)t * BATCH + b) * NOUT + n0;
        *(float4*)(orow)     = make_float4(sp[0], sp[1], sp[2], sp[3]);
        *(float4*)(orow + 4) = make_float4(sp[4], sp[5], sp[6], sp[7]);

        // decoder partial dots: pd[c] = sum_j sp[j] * Wdec[c][n0+j]
        float pd[NC];
#pragma unroll
        for (int c = 0; c < NC; c++) {
            const float4 w0 = *(const float4*)(Wdec + (size_t)c * NOUT + n0);
            const float4 w1 = *(const float4*)(Wdec + (size_t)c * NOUT + n0 + 4);
            float d;
            d  = sp[0] * w0.x; d = fmaf(sp[1], w0.y, d);
            d  = fmaf(sp[2], w0.z, d); d = fmaf(sp[3], w0.w, d);
            d  = fmaf(sp[4], w1.x, d); d = fmaf(sp[5], w1.y, d);
            d  = fmaf(sp[6], w1.z, d); d = fmaf(sp[7], w1.w, d);
            pd[c] = d;
        }
        // warp reduce each class
#pragma unroll
        for (int c = 0; c < NC; c++) {
#pragma unroll
            for (int off = 16; off > 0; off >>= 1)
                pd[c] += __shfl_xor_sync(0xffffffffu, pd[c], off);
        }
        if (lane == 0) {
#pragma unroll
            for (int c = 0; c < NC; c++) red[wid][c] = pd[c];
        }
        __syncthreads();

        if (tid < NC) {
            float d = 0.0f;
#pragma unroll
            for (int w = 0; w < 8; w++) d += red[w][tid];
            ym = ym * DECAY + d - ys * TD;
            ys = (ym > THRESH) ? 1.0f : 0.0f;
            const float e = ys - yoh;
            lossacc = fmaf(e, e, lossacc);
        }
        __syncthreads();   // protect red[] before next step overwrites
    }

    if (tid < NC) lsh[tid] = lossacc;
    __syncthreads();
    if (tid == 0) {
        float s = 0.0f;
#pragma unroll
        for (int c = 0; c < NC; c++) s += lsh[c];
        g_losspart[b] = s;
    }
}

// ---------------------------------------------------------------------------
// Kernel 3: reduce per-b loss partials -> scalar loss at out[T*B*NOUT]
// ---------------------------------------------------------------------------
__global__ void loss_reduce_kernel(float* __restrict__ out)
{
    __shared__ float sh[256];
    const int tid = threadIdx.x;
    float s = 0.0f;
    for (int i = tid; i < BATCH; i += 256) s += g_losspart[i];
    sh[tid] = s;
    __syncthreads();
    for (int off = 128; off > 0; off >>= 1) {
        if (tid < off) sh[tid] += sh[tid + off];
        __syncthreads();
    }
    if (tid == 0)
        out[(size_t)TSTEPS * BATCH * NOUT] = sh[0] / (float)(BATCH * NC);
}

// ---------------------------------------------------------------------------
// Launch
// ---------------------------------------------------------------------------
extern "C" void kernel_launch(void* const* d_in, const int* in_sizes, int n_in,
                              void* d_out, int out_size)
{
    const float* x    = (const float*)d_in[0];   // [B, NIN]
    const float* Wenc = (const float*)d_in[1];   // [NOUT, NIN]
    const float* Wdec = (const float*)d_in[2];   // [NC, NOUT]
    const float* y1h  = (const float*)d_in[3];   // [B, NC]
    float* out = (float*)d_out;

    dim3 ggrid(NOUT / BN, BATCH / BM);           // (16, 8)
    sgemm_nt_kernel<<<ggrid, 256>>>(x, Wenc);

    lif_fused_kernel<<<BATCH, 256>>>(Wdec, y1h, out);

    if (out_size > TSTEPS * BATCH * NOUT) {
        loss_reduce_kernel<<<1, 256>>>(out);
    }
}

// round 6
// speedup vs baseline: 1.3752x; 1.3752x over previous
#include <cuda_runtime.h>
#include <cstdint>

#define BATCH 1024
#define NIN   2048
#define NOUT  2048
#define NC    10
#define TSTEPS 10

// ---------------------------------------------------------------------------
// Device scratch (no cudaMalloc allowed)
// ---------------------------------------------------------------------------
__device__ float g_h [BATCH * NOUT];   // 8 MB  h = x @ W_enc^T
__device__ float g_dec[TSTEPS * BATCH * NC];

// ---------------------------------------------------------------------------
// f32x2 packed helpers (sm_100+ PTX, not arch-'a' gated)
// ---------------------------------------------------------------------------
typedef unsigned long long u64t;

__device__ __forceinline__ u64t dup2(float b) {
    u64t d;
    asm("mov.b64 %0, {%1, %1};" : "=l"(d) : "f"(b));
    return d;
}
__device__ __forceinline__ void ffma2(u64t& acc, u64t a, u64t b) {
    asm("fma.rn.f32x2 %0, %1, %2, %0;" : "+l"(acc) : "l"(a), "l"(b));
}
__device__ __forceinline__ void unpack2(u64t v, float& lo, float& hi) {
    asm("mov.b64 {%0, %1}, %2;" : "=f"(lo), "=f"(hi) : "l"(v));
}

// ---------------------------------------------------------------------------
// SGEMM (fp32, FFMA2): H[m][n] = sum_k x[m][k] * W[n][k]
// CTA tile 128x128, 256 threads, 8x8 per thread (m packed in f32x2 pairs).
// BK=16, transposed smem tiles As[k][m], Bs[k][n], double buffered.
// Serial-K accumulation per thread (matches reference fp32 error structure).
// ---------------------------------------------------------------------------
#define BM 128
#define BN 128
#define BK 16
#define LDT 132    // row stride in floats (528 B, 16B-aligned)

__global__ __launch_bounds__(256, 1)
void sgemm2_kernel(const float* __restrict__ A, const float* __restrict__ Bw)
{
    __shared__ float As[2][BK][LDT];
    __shared__ float Bs[2][BK][LDT];

    const int tid = threadIdx.x;
    const int m0  = blockIdx.y * BM;
    const int n0  = blockIdx.x * BN;

    // loader mapping: rows r, r+64 ; 16-float k-chunk start c4
    const int r  = tid >> 2;          // 0..63
    const int c4 = (tid & 3) << 2;    // 0,4,8,12

    // compute mapping
    const int tx = tid & 15;          // n group (8 cols)
    const int ty = tid >> 4;          // m group (8 rows)

    const float* pA0 = A  + (size_t)(m0 + r)      * NIN + c4;
    const float* pA1 = A  + (size_t)(m0 + r + 64) * NIN + c4;
    const float* pB0 = Bw + (size_t)(n0 + r)      * NIN + c4;
    const float* pB1 = Bw + (size_t)(n0 + r + 64) * NIN + c4;

    u64t acc[4][8];
#pragma unroll
    for (int i = 0; i < 4; i++)
#pragma unroll
        for (int j = 0; j < 8; j++) acc[i][j] = 0ull;

    // prologue: tile 0 -> smem buf 0
    {
        float4 a0 = *(const float4*)(pA0);
        float4 a1 = *(const float4*)(pA1);
        float4 b0 = *(const float4*)(pB0);
        float4 b1 = *(const float4*)(pB1);
        const float av0[4] = {a0.x, a0.y, a0.z, a0.w};
        const float av1[4] = {a1.x, a1.y, a1.z, a1.w};
        const float bv0[4] = {b0.x, b0.y, b0.z, b0.w};
        const float bv1[4] = {b1.x, b1.y, b1.z, b1.w};
#pragma unroll
        for (int j = 0; j < 4; j++) {
            As[0][c4 + j][r]      = av0[j];
            As[0][c4 + j][r + 64] = av1[j];
            Bs[0][c4 + j][r]      = bv0[j];
            Bs[0][c4 + j][r + 64] = bv1[j];
        }
    }
    __syncthreads();

    int p = 0;
    const int NITER = NIN / BK;       // 128
    for (int it = 0; it < NITER; it++) {
        float4 a0, a1, b0, b1;
        if (it + 1 < NITER) {
            const int ko = (it + 1) * BK;
            a0 = *(const float4*)(pA0 + ko);
            a1 = *(const float4*)(pA1 + ko);
            b0 = *(const float4*)(pB0 + ko);
            b1 = *(const float4*)(pB1 + ko);
        }

#pragma unroll
        for (int kk = 0; kk < BK; kk++) {
            // a pairs: 8 m-floats = 4 f32x2, direct from smem
            const u64t* ap = (const u64t*)&As[p][kk][ty * 8];
            u64t a2[4];
            a2[0] = ap[0]; a2[1] = ap[1]; a2[2] = ap[2]; a2[3] = ap[3];
            // b: 8 n-floats, duplicate into both lanes
            const float* bp = &Bs[p][kk][tx * 8];
            u64t bd[8];
#pragma unroll
            for (int j = 0; j < 8; j++) bd[j] = dup2(bp[j]);
#pragma unroll
            for (int i = 0; i < 4; i++)
#pragma unroll
                for (int j = 0; j < 8; j++)
                    ffma2(acc[i][j], a2[i], bd[j]);
        }

        if (it + 1 < NITER) {
            const int q = p ^ 1;
            const float av0[4] = {a0.x, a0.y, a0.z, a0.w};
            const float av1[4] = {a1.x, a1.y, a1.z, a1.w};
            const float bv0[4] = {b0.x, b0.y, b0.z, b0.w};
            const float bv1[4] = {b1.x, b1.y, b1.z, b1.w};
#pragma unroll
            for (int j = 0; j < 4; j++) {
                As[q][c4 + j][r]      = av0[j];
                As[q][c4 + j][r + 64] = av1[j];
                Bs[q][c4 + j][r]      = bv0[j];
                Bs[q][c4 + j][r + 64] = bv1[j];
            }
            __syncthreads();
            p = q;
        }
    }

    // epilogue: acc[i][j] lanes = rows (ty*8+2i, ty*8+2i+1), col n0+tx*8+j
#pragma unroll
    for (int i = 0; i < 4; i++) {
        float lo[8], hi[8];
#pragma unroll
        for (int j = 0; j < 8; j++) unpack2(acc[i][j], lo[j], hi[j]);
        const int row_e = m0 + ty * 8 + 2 * i;
        float* d0 = g_h + (size_t)row_e * NOUT + n0 + tx * 8;
        float* d1 = d0 + NOUT;
        *(float4*)(d0)     = make_float4(lo[0], lo[1], lo[2], lo[3]);
        *(float4*)(d0 + 4) = make_float4(lo[4], lo[5], lo[6], lo[7]);
        *(float4*)(d1)     = make_float4(hi[0], hi[1], hi[2], hi[3]);
        *(float4*)(d1 + 4) = make_float4(hi[4], hi[5], hi[6], hi[7]);
    }
}

// ---------------------------------------------------------------------------
// Kernel 2: pure LIF spike recurrence (elementwise, streaming).
// ---------------------------------------------------------------------------
__global__ __launch_bounds__(256)
void lif_kernel(float* __restrict__ out)
{
    const int idx = blockIdx.x * 256 + threadIdx.x;
    const int b = idx >> 8;
    const int n = (idx & 255) << 3;

    const float* hp = g_h + (size_t)b * NOUT + n;
    const float4 h0 = *(const float4*)(hp);
    const float4 h1 = *(const float4*)(hp + 4);
    const float h[8] = {h0.x, h0.y, h0.z, h0.w, h1.x, h1.y, h1.z, h1.w};

    float m[8], s[8];
#pragma unroll
    for (int j = 0; j < 8; j++) { m[j] = 0.0f; s[j] = 0.0f; }

#pragma unroll
    for (int t = 0; t < TSTEPS; t++) {
#pragma unroll
        for (int j = 0; j < 8; j++) {
            m[j] = m[j] * 0.2f + h[j] - s[j] * 0.1f;
            s[j] = (m[j] > 0.5f) ? 1.0f : 0.0f;
        }
        float* o = out + ((size_t)t * BATCH + b) * NOUT + n;
        *(float4*)(o)     = make_float4(s[0], s[1], s[2], s[3]);
        *(float4*)(o + 4) = make_float4(s[4], s[5], s[6], s[7]);
    }
}

// ---------------------------------------------------------------------------
// Kernel 3: decoder GEMV  g_dec[t][b][c] = spikes[t,b,:] . Wdec[c,:]
// ---------------------------------------------------------------------------
__global__ __launch_bounds__(256)
void dec_kernel(const float* __restrict__ spikes, const float* __restrict__ Wdec)
{
    const int gw = blockIdx.x * 8 + (threadIdx.x >> 5);   // t*B+b
    const int lane = threadIdx.x & 31;
    const float* srow = spikes + (size_t)gw * NOUT;

    float acc[NC];
#pragma unroll
    for (int c = 0; c < NC; c++) acc[c] = 0.0f;

#pragma unroll
    for (int j = 0; j < 16; j++) {
        const int col = j * 128 + lane * 4;
        const float4 sv = *(const float4*)(srow + col);
#pragma unroll
        for (int c = 0; c < NC; c++) {
            const float4 w = *(const float4*)(Wdec + (size_t)c * NOUT + col);
            acc[c] = fmaf(sv.x, w.x,
                     fmaf(sv.y, w.y,
                     fmaf(sv.z, w.z,
                     fmaf(sv.w, w.w, acc[c]))));
        }
    }
#pragma unroll
    for (int c = 0; c < NC; c++) {
        float v = acc[c];
#pragma unroll
        for (int off = 16; off > 0; off >>= 1)
            v += __shfl_xor_sync(0xffffffffu, v, off);
        if (lane == 0) g_dec[(size_t)gw * NC + c] = v;
    }
}

// ---------------------------------------------------------------------------
// Kernel 4: decoder LIF recurrence + MSE loss.
// ---------------------------------------------------------------------------
__global__ void final_kernel(const float* __restrict__ y1h, float* __restrict__ out)
{
    __shared__ float sh[1024];
    const int b = threadIdx.x;

    float ym[NC], ys[NC], yoh[NC];
#pragma unroll
    for (int c = 0; c < NC; c++) {
        ym[c] = 0.0f; ys[c] = 0.0f;
        yoh[c] = y1h[(size_t)b * NC + c];
    }
    float loss = 0.0f;
#pragma unroll
    for (int t = 0; t < TSTEPS; t++) {
#pragma unroll
        for (int c = 0; c < NC; c++) {
            const float d = g_dec[((size_t)t * BATCH + b) * NC + c];
            ym[c] = ym[c] * 0.2f + d - ys[c] * 0.1f;
            ys[c] = (ym[c] > 0.5f) ? 1.0f : 0.0f;
            const float e = ys[c] - yoh[c];
            loss = fmaf(e, e, loss);
        }
    }
    sh[b] = loss;
    __syncthreads();
    for (int off = 512; off > 0; off >>= 1) {
        if (b < off) sh[b] += sh[b + off];
        __syncthreads();
    }
    if (b == 0)
        out[(size_t)TSTEPS * BATCH * NOUT] = sh[0] / (float)(BATCH * NC);
}

// ---------------------------------------------------------------------------
// Launch
// ---------------------------------------------------------------------------
extern "C" void kernel_launch(void* const* d_in, const int* in_sizes, int n_in,
                              void* d_out, int out_size)
{
    const float* x    = (const float*)d_in[0];
    const float* Wenc = (const float*)d_in[1];
    const float* Wdec = (const float*)d_in[2];
    const float* y1h  = (const float*)d_in[3];
    float* out = (float*)d_out;

    dim3 ggrid(NOUT / BN, BATCH / BM);           // (16, 8) = 128 CTAs
    sgemm2_kernel<<<ggrid, 256>>>(x, Wenc);
    lif_kernel<<<1024, 256>>>(out);
    dec_kernel<<<1280, 256>>>(out, Wdec);
    if (out_size > TSTEPS * BATCH * NOUT)
        final_kernel<<<1, 1024>>>(y1h, out);
}

// round 11
// speedup vs baseline: 1.3888x; 1.0099x over previous
#include <cuda_runtime.h>
#include <cstdint>

#define BATCH 1024
#define NIN   2048
#define NOUT  2048
#define NC    10
#define TSTEPS 10

// ---------------------------------------------------------------------------
// Device scratch (no cudaMalloc allowed)
// ---------------------------------------------------------------------------
__device__ float g_h [BATCH * NOUT];   // 8 MB  h = x @ W_enc^T
__device__ float g_dec[TSTEPS * BATCH * NC];
__device__ float g_losspart[BATCH];

// ---------------------------------------------------------------------------
// f32x2 packed helpers (sm_100+ PTX, not arch-'a' gated)
// ---------------------------------------------------------------------------
typedef unsigned long long u64t;

__device__ __forceinline__ u64t dup2(float b) {
    u64t d;
    asm("mov.b64 %0, {%1, %1};" : "=l"(d) : "f"(b));
    return d;
}
__device__ __forceinline__ void ffma2(u64t& acc, u64t a, u64t b) {
    asm("fma.rn.f32x2 %0, %1, %2, %0;" : "+l"(acc) : "l"(a), "l"(b));
}
__device__ __forceinline__ void unpack2(u64t v, float& lo, float& hi) {
    asm("mov.b64 {%0, %1}, %2;" : "=f"(lo), "=f"(hi) : "l"(v));
}

// staggered column placement: column r -> float offset r + (r>>5)*4
// (16 8-float chunks per row start at banks {0,8,16,24,4,12,20,28,...}
//  -> every 4-bank group covered exactly twice -> 2-phase LDS.128, no conflicts)
__device__ __forceinline__ int colmap(int r) { return r + ((r >> 5) << 2); }

// ---------------------------------------------------------------------------
// SGEMM (fp32, FFMA2): H[m][n] = sum_k x[m][k] * W[n][k]
// CTA tile 128x128, 256 threads, 8x8 per thread (m packed in f32x2 pairs).
// BK=16, transposed smem tiles As[k][m], Bs[k][n] (staggered), double buffer.
// Serial-K accumulation per thread (matches reference fp32 error structure).
// ---------------------------------------------------------------------------
#define BM 128
#define BN 128
#define BK 16
#define LDT 148    // staggered row stride in floats (592 B, 16B-aligned)

__global__ __launch_bounds__(256, 1)
void sgemm2_kernel(const float* __restrict__ A, const float* __restrict__ Bw)
{
    __shared__ float As[2][BK][LDT];
    __shared__ float Bs[2][BK][LDT];

    const int tid = threadIdx.x;
    const int m0  = blockIdx.y * BM;
    const int n0  = blockIdx.x * BN;

    // loader mapping: rows r, r+64 ; 16-float k-chunk start c4
    const int r  = tid >> 2;          // 0..63
    const int c4 = (tid & 3) << 2;    // 0,4,8,12
    const int wr0 = colmap(r);        // staggered write offsets
    const int wr1 = colmap(r + 64);

    // compute mapping
    const int tx = tid & 15;          // n group (8 cols)
    const int ty = tid >> 4;          // m group (8 rows)
    const int abase = ty * 8 + ((ty >> 2) << 2);   // staggered read bases
    const int bbase = tx * 8 + ((tx >> 2) << 2);

    const float* pA0 = A  + (size_t)(m0 + r)      * NIN + c4;
    const float* pA1 = A  + (size_t)(m0 + r + 64) * NIN + c4;
    const float* pB0 = Bw + (size_t)(n0 + r)      * NIN + c4;
    const float* pB1 = Bw + (size_t)(n0 + r + 64) * NIN + c4;

    u64t acc[4][8];
#pragma unroll
    for (int i = 0; i < 4; i++)
#pragma unroll
        for (int j = 0; j < 8; j++) acc[i][j] = 0ull;

    // prologue: tile 0 -> smem buf 0
    {
        float4 a0 = *(const float4*)(pA0);
        float4 a1 = *(const float4*)(pA1);
        float4 b0 = *(const float4*)(pB0);
        float4 b1 = *(const float4*)(pB1);
        const float av0[4] = {a0.x, a0.y, a0.z, a0.w};
        const float av1[4] = {a1.x, a1.y, a1.z, a1.w};
        const float bv0[4] = {b0.x, b0.y, b0.z, b0.w};
        const float bv1[4] = {b1.x, b1.y, b1.z, b1.w};
#pragma unroll
        for (int j = 0; j < 4; j++) {
            As[0][c4 + j][wr0] = av0[j];
            As[0][c4 + j][wr1] = av1[j];
            Bs[0][c4 + j][wr0] = bv0[j];
            Bs[0][c4 + j][wr1] = bv1[j];
        }
    }
    __syncthreads();

    int p = 0;
    const int NITER = NIN / BK;       // 128
    for (int it = 0; it < NITER; it++) {
        float4 a0, a1, b0, b1;
        if (it + 1 < NITER) {
            const int ko = (it + 1) * BK;
            a0 = *(const float4*)(pA0 + ko);
            a1 = *(const float4*)(pA1 + ko);
            b0 = *(const float4*)(pB0 + ko);
            b1 = *(const float4*)(pB1 + ko);
        }

#pragma unroll
        for (int kk = 0; kk < BK; kk++) {
            // a pairs: 8 m-floats = 4 f32x2, direct from smem (broadcast)
            const u64t* ap = (const u64t*)&As[p][kk][abase];
            u64t a2[4];
            a2[0] = ap[0]; a2[1] = ap[1]; a2[2] = ap[2]; a2[3] = ap[3];
            // b: 8 n-floats (2x LDS.128, conflict-free), duplicate lanes
            const float* bp = &Bs[p][kk][bbase];
            const float4 bq0 = *(const float4*)(bp);
            const float4 bq1 = *(const float4*)(bp + 4);
            u64t bd[8];
            bd[0] = dup2(bq0.x); bd[1] = dup2(bq0.y);
            bd[2] = dup2(bq0.z); bd[3] = dup2(bq0.w);
            bd[4] = dup2(bq1.x); bd[5] = dup2(bq1.y);
            bd[6] = dup2(bq1.z); bd[7] = dup2(bq1.w);
#pragma unroll
            for (int i = 0; i < 4; i++)
#pragma unroll
                for (int j = 0; j < 8; j++)
                    ffma2(acc[i][j], a2[i], bd[j]);
        }

        if (it + 1 < NITER) {
            const int q = p ^ 1;
            const float av0[4] = {a0.x, a0.y, a0.z, a0.w};
            const float av1[4] = {a1.x, a1.y, a1.z, a1.w};
            const float bv0[4] = {b0.x, b0.y, b0.z, b0.w};
            const float bv1[4] = {b1.x, b1.y, b1.z, b1.w};
#pragma unroll
            for (int j = 0; j < 4; j++) {
                As[q][c4 + j][wr0] = av0[j];
                As[q][c4 + j][wr1] = av1[j];
                Bs[q][c4 + j][wr0] = bv0[j];
                Bs[q][c4 + j][wr1] = bv1[j];
            }
            __syncthreads();
            p = q;
        }
    }

    // epilogue: acc[i][j] lanes = rows (ty*8+2i, ty*8+2i+1), col n0+tx*8+j
#pragma unroll
    for (int i = 0; i < 4; i++) {
        float lo[8], hi[8];
#pragma unroll
        for (int j = 0; j < 8; j++) unpack2(acc[i][j], lo[j], hi[j]);
        const int row_e = m0 + ty * 8 + 2 * i;
        float* d0 = g_h + (size_t)row_e * NOUT + n0 + tx * 8;
        float* d1 = d0 + NOUT;
        *(float4*)(d0)     = make_float4(lo[0], lo[1], lo[2], lo[3]);
        *(float4*)(d0 + 4) = make_float4(lo[4], lo[5], lo[6], lo[7]);
        *(float4*)(d1)     = make_float4(hi[0], hi[1], hi[2], hi[3]);
        *(float4*)(d1 + 4) = make_float4(hi[4], hi[5], hi[6], hi[7]);
    }
}

// ---------------------------------------------------------------------------
// Kernel 2: pure LIF spike recurrence (elementwise, streaming).
// ---------------------------------------------------------------------------
__global__ __launch_bounds__(256)
void lif_kernel(float* __restrict__ out)
{
    const int idx = blockIdx.x * 256 + threadIdx.x;
    const int b = idx >> 8;
    const int n = (idx & 255) << 3;

    const float* hp = g_h + (size_t)b * NOUT + n;
    const float4 h0 = *(const float4*)(hp);
    const float4 h1 = *(const float4*)(hp + 4);
    const float h[8] = {h0.x, h0.y, h0.z, h0.w, h1.x, h1.y, h1.z, h1.w};

    float m[8], s[8];
#pragma unroll
    for (int j = 0; j < 8; j++) { m[j] = 0.0f; s[j] = 0.0f; }

#pragma unroll
    for (int t = 0; t < TSTEPS; t++) {
#pragma unroll
        for (int j = 0; j < 8; j++) {
            m[j] = m[j] * 0.2f + h[j] - s[j] * 0.1f;
            s[j] = (m[j] > 0.5f) ? 1.0f : 0.0f;
        }
        float* o = out + ((size_t)t * BATCH + b) * NOUT + n;
        *(float4*)(o)     = make_float4(s[0], s[1], s[2], s[3]);
        *(float4*)(o + 4) = make_float4(s[4], s[5], s[6], s[7]);
    }
}

// ---------------------------------------------------------------------------
// Kernel 3: decoder GEMV  g_dec[t][b][c] = spikes[t,b,:] . Wdec[c,:]
// ---------------------------------------------------------------------------
__global__ __launch_bounds__(256)
void dec_kernel(const float* __restrict__ spikes, const float* __restrict__ Wdec)
{
    const int gw = blockIdx.x * 8 + (threadIdx.x >> 5);   // t*B+b
    const int lane = threadIdx.x & 31;
    const float* srow = spikes + (size_t)gw * NOUT;

    float acc[NC];
#pragma unroll
    for (int c = 0; c < NC; c++) acc[c] = 0.0f;

#pragma unroll
    for (int j = 0; j < 16; j++) {
        const int col = j * 128 + lane * 4;
        const float4 sv = *(const float4*)(srow + col);
#pragma unroll
        for (int c = 0; c < NC; c++) {
            const float4 w = *(const float4*)(Wdec + (size_t)c * NOUT + col);
            acc[c] = fmaf(sv.x, w.x,
                     fmaf(sv.y, w.y,
                     fmaf(sv.z, w.z,
                     fmaf(sv.w, w.w, acc[c]))));
        }
    }
#pragma unroll
    for (int c = 0; c < NC; c++) {
        float v = acc[c];
#pragma unroll
        for (int off = 16; off > 0; off >>= 1)
            v += __shfl_xor_sync(0xffffffffu, v, off);
        if (lane == 0) g_dec[(size_t)gw * NC + c] = v;
    }
}

// ---------------------------------------------------------------------------
// Kernel 4a: per-batch-row decoder LIF recurrence + MSE loss partial.
// ---------------------------------------------------------------------------
__global__ __launch_bounds__(128)
void loss_kernel(const float* __restrict__ y1h)
{
    const int b = blockIdx.x * 128 + threadIdx.x;   // 0..1023

    float ym[NC], ys[NC], yoh[NC];
#pragma unroll
    for (int c = 0; c < NC; c++) {
        ym[c] = 0.0f; ys[c] = 0.0f;
        yoh[c] = y1h[(size_t)b * NC + c];
    }
    float loss = 0.0f;
#pragma unroll
    for (int t = 0; t < TSTEPS; t++) {
#pragma unroll
        for (int c = 0; c < NC; c++) {
            const float d = g_dec[((size_t)t * BATCH + b) * NC + c];
            ym[c] = ym[c] * 0.2f + d - ys[c] * 0.1f;
            ys[c] = (ym[c] > 0.5f) ? 1.0f : 0.0f;
            const float e = ys[c] - yoh[c];
            loss = fmaf(e, e, loss);
        }
    }
    g_losspart[b] = loss;
}

// ---------------------------------------------------------------------------
// Kernel 4b: deterministic reduce of 1024 loss partials -> scalar.
// ---------------------------------------------------------------------------
__global__ void loss_reduce_kernel(float* __restrict__ out)
{
    __shared__ float sh[256];
    const int tid = threadIdx.x;
    float s = 0.0f;
    for (int i = tid; i < BATCH; i += 256) s += g_losspart[i];
    sh[tid] = s;
    __syncthreads();
    for (int off = 128; off > 0; off >>= 1) {
        if (tid < off) sh[tid] += sh[tid + off];
        __syncthreads();
    }
    if (tid == 0)
        out[(size_t)TSTEPS * BATCH * NOUT] = sh[0] / (float)(BATCH * NC);
}

// ---------------------------------------------------------------------------
// Launch
// ---------------------------------------------------------------------------
extern "C" void kernel_launch(void* const* d_in, const int* in_sizes, int n_in,
                              void* d_out, int out_size)
{
    const float* x    = (const float*)d_in[0];
    const float* Wenc = (const float*)d_in[1];
    const float* Wdec = (const float*)d_in[2];
    const float* y1h  = (const float*)d_in[3];
    float* out = (float*)d_out;

    dim3 ggrid(NOUT / BN, BATCH / BM);           // (16, 8) = 128 CTAs
    sgemm2_kernel<<<ggrid, 256>>>(x, Wenc);
    lif_kernel<<<1024, 256>>>(out);
    dec_kernel<<<1280, 256>>>(out, Wdec);
    if (out_size > TSTEPS * BATCH * NOUT) {
        loss_kernel<<<8, 128>>>(y1h);
        loss_reduce_kernel<<<1, 256>>>(out);
    }
}